// round 2
// baseline (speedup 1.0000x reference)
#include <cuda_runtime.h>

// Problem constants
#define BV   8
#define CV   19
#define HWv  (512 * 1024)              // 524288 = 2^19
#define NPIX (BV * HWv)                // 4194304
#define THREADS 256
#define PIX_PER_THREAD 4
#define NBLOCKS (NPIX / (THREADS * PIX_PER_THREAD))   // 4096

__device__ float        g_partials[NBLOCKS];
__device__ unsigned int g_count = 0;   // block-arrival counter (reset each call)

__global__ __launch_bounds__(THREADS)
void ce_fused_kernel(const float* __restrict__ logits,
                     const int*   __restrict__ labels,
                     float*       __restrict__ out) {
    const int tid  = blockIdx.x * THREADS + threadIdx.x;
    const int base = tid * PIX_PER_THREAD;          // first pixel of this thread
    const int b    = base >> 19;                    // image index (HW = 2^19)
    const int pix  = base & (HWv - 1);              // pixel within image

    const float4* lp =
        reinterpret_cast<const float4*>(logits + (size_t)b * CV * HWv + pix);
    const int4 lab = *reinterpret_cast<const int4*>(labels + base);

    float4 s  = make_float4(0.f, 0.f, 0.f, 0.f);
    float4 xl = make_float4(0.f, 0.f, 0.f, 0.f);

    #pragma unroll
    for (int c = 0; c < CV; ++c) {
        const float4 v = lp[c * (HWv / 4)];
        s.x += __expf(v.x);
        s.y += __expf(v.y);
        s.z += __expf(v.z);
        s.w += __expf(v.w);
        if (c == lab.x) xl.x = v.x;
        if (c == lab.y) xl.y = v.y;
        if (c == lab.z) xl.z = v.z;
        if (c == lab.w) xl.w = v.w;
    }

    // nll = log(sum exp) - x_label ; zero at ignored pixels (label < 0)
    float loss = 0.f;
    loss += (lab.x >= 0) ? (__logf(s.x) - xl.x) : 0.f;
    loss += (lab.y >= 0) ? (__logf(s.y) - xl.y) : 0.f;
    loss += (lab.z >= 0) ? (__logf(s.z) - xl.z) : 0.f;
    loss += (lab.w >= 0) ? (__logf(s.w) - xl.w) : 0.f;

    // warp reduce
    #pragma unroll
    for (int o = 16; o > 0; o >>= 1)
        loss += __shfl_down_sync(0xFFFFFFFFu, loss, o);

    __shared__ float ws[THREADS / 32];
    __shared__ bool  s_is_last;
    if ((threadIdx.x & 31) == 0) ws[threadIdx.x >> 5] = loss;
    __syncthreads();

    if (threadIdx.x < (THREADS / 32)) {
        float v = ws[threadIdx.x];
        #pragma unroll
        for (int o = (THREADS / 64); o > 0; o >>= 1)
            v += __shfl_down_sync(0xFFu, v, o);
        if (threadIdx.x == 0) g_partials[blockIdx.x] = v;
    }

    // ---- last-block finalization (deterministic: fixed summation order) ----
    if (threadIdx.x == 0) {
        __threadfence();  // make g_partials[blockIdx.x] visible
        unsigned int prev = atomicInc(&g_count, NBLOCKS - 1);
        s_is_last = (prev == NBLOCKS - 1);   // atomicInc wraps counter to 0 here
    }
    __syncthreads();
    if (!s_is_last) return;

    // this block sums all partials in fixed strided order
    float acc = 0.f;
    #pragma unroll
    for (int i = threadIdx.x; i < NBLOCKS; i += THREADS)
        acc += g_partials[i];

    #pragma unroll
    for (int o = 16; o > 0; o >>= 1)
        acc += __shfl_down_sync(0xFFFFFFFFu, acc, o);

    __syncthreads();   // reuse ws safely
    if ((threadIdx.x & 31) == 0) ws[threadIdx.x >> 5] = acc;
    __syncthreads();

    if (threadIdx.x == 0) {
        float v = 0.f;
        #pragma unroll
        for (int w = 0; w < THREADS / 32; ++w) v += ws[w];
        out[0] = v * (1.0f / (float)NPIX);
    }
}

extern "C" void kernel_launch(void* const* d_in, const int* in_sizes, int n_in,
                              void* d_out, int out_size) {
    const float* logits = (const float*)d_in[0];
    const int*   labels = (const int*)d_in[1];
    // d_in[2] (smooth_labels) is dead in the reference forward — never read.
    float* out = (float*)d_out;

    ce_fused_kernel<<<NBLOCKS, THREADS>>>(logits, labels, out);
}

// round 3
// speedup vs baseline: 1.0858x; 1.0858x over previous
#include <cuda_runtime.h>

// Problem constants
#define BV   8
#define CV   19
#define HWv  (512 * 1024)              // 524288 = 2^19
#define NPIX (BV * HWv)                // 4194304
#define THREADS 256
#define PIX_PER_THREAD 4
#define NBLOCKS (NPIX / (THREADS * PIX_PER_THREAD))   // 4096

__device__ float g_partials[NBLOCKS];

__global__ __launch_bounds__(THREADS)
void ce_main_kernel(const float* __restrict__ logits,
                    const int*   __restrict__ labels) {
    const int tid  = blockIdx.x * THREADS + threadIdx.x;
    const int base = tid * PIX_PER_THREAD;          // first pixel of this thread
    const int b    = base >> 19;                    // image index (HW = 2^19)
    const int pix  = base & (HWv - 1);              // pixel within image

    const float4* lp =
        reinterpret_cast<const float4*>(logits + (size_t)b * CV * HWv + pix);
    const int4 lab = __ldcs(reinterpret_cast<const int4*>(labels + base));

    float4 s  = make_float4(0.f, 0.f, 0.f, 0.f);
    float4 xl = make_float4(0.f, 0.f, 0.f, 0.f);

    #pragma unroll
    for (int c = 0; c < CV; ++c) {
        const float4 v = __ldcs(lp + c * (HWv / 4));   // streaming: evict-first
        s.x += __expf(v.x);
        s.y += __expf(v.y);
        s.z += __expf(v.z);
        s.w += __expf(v.w);
        if (c == lab.x) xl.x = v.x;
        if (c == lab.y) xl.y = v.y;
        if (c == lab.z) xl.z = v.z;
        if (c == lab.w) xl.w = v.w;
    }

    // nll = log(sum exp) - x_label ; zero at ignored pixels (label < 0)
    float loss = 0.f;
    loss += (lab.x >= 0) ? (__logf(s.x) - xl.x) : 0.f;
    loss += (lab.y >= 0) ? (__logf(s.y) - xl.y) : 0.f;
    loss += (lab.z >= 0) ? (__logf(s.z) - xl.z) : 0.f;
    loss += (lab.w >= 0) ? (__logf(s.w) - xl.w) : 0.f;

    // warp reduce
    #pragma unroll
    for (int o = 16; o > 0; o >>= 1)
        loss += __shfl_down_sync(0xFFFFFFFFu, loss, o);

    __shared__ float ws[THREADS / 32];
    if ((threadIdx.x & 31) == 0) ws[threadIdx.x >> 5] = loss;
    __syncthreads();

    if (threadIdx.x < (THREADS / 32)) {
        float v = ws[threadIdx.x];
        #pragma unroll
        for (int o = (THREADS / 64); o > 0; o >>= 1)
            v += __shfl_down_sync(0xFFu, v, o);
        if (threadIdx.x == 0) g_partials[blockIdx.x] = v;
    }
}

// Secondary kernel: launched with PDL so its launch latency overlaps the
// primary. Waits on the grid dependency before reading g_partials.
__global__ __launch_bounds__(256)
void ce_reduce_kernel(float* __restrict__ out) {
    cudaGridDependencySynchronize();

    // 4096 floats = 1024 float4; 256 threads x 4 float4 each, MLP=4
    const float4* p = reinterpret_cast<const float4*>(g_partials);
    float s = 0.f;
    #pragma unroll
    for (int i = 0; i < 4; ++i) {
        float4 v = p[threadIdx.x + i * 256];
        s += (v.x + v.y) + (v.z + v.w);
    }

    #pragma unroll
    for (int o = 16; o > 0; o >>= 1)
        s += __shfl_down_sync(0xFFFFFFFFu, s, o);

    __shared__ float ws[8];
    if ((threadIdx.x & 31) == 0) ws[threadIdx.x >> 5] = s;
    __syncthreads();

    if (threadIdx.x == 0) {
        float v = 0.f;
        #pragma unroll
        for (int w = 0; w < 8; ++w) v += ws[w];
        out[0] = v * (1.0f / (float)NPIX);
    }
}

extern "C" void kernel_launch(void* const* d_in, const int* in_sizes, int n_in,
                              void* d_out, int out_size) {
    const float* logits = (const float*)d_in[0];
    const int*   labels = (const int*)d_in[1];
    // d_in[2] (smooth_labels) is dead in the reference forward — never read.
    float* out = (float*)d_out;

    ce_main_kernel<<<NBLOCKS, THREADS>>>(logits, labels);

    // PDL launch of the reduce: overlap its launch with the primary's tail.
    cudaLaunchConfig_t cfg = {};
    cfg.gridDim  = dim3(1, 1, 1);
    cfg.blockDim = dim3(256, 1, 1);
    cfg.dynamicSmemBytes = 0;
    cfg.stream = 0;
    cudaLaunchAttribute attr[1];
    attr[0].id = cudaLaunchAttributeProgrammaticStreamSerialization;
    attr[0].val.programmaticStreamSerializationAllowed = 1;
    cfg.attrs = attr;
    cfg.numAttrs = 1;
    cudaLaunchKernelEx(&cfg, ce_reduce_kernel, out);
}